// round 1
// baseline (speedup 1.0000x reference)
#include <cuda_runtime.h>
#include <math.h>

#define NN 2000
#define BB 64
#define EMBED 512
#define LABELS 20
#define NC 31   // Taylor coefficients: degree 30

// ---- scratch (no allocation allowed -> __device__ globals) ----
__device__ float g_XT[NN * BB];          // XT[m][b]
__device__ float g_mixedT[NN * BB];      // mixedT[n][b]
__device__ float g_part1[4 * NN * BB];   // split-K partials for IG gemm
__device__ float g_part2[8 * EMBED * BB];
__device__ float g_hT[EMBED * BB];       // hidden transposed [e][b]
__device__ float g_cn[NC][BB];           // numerator coeffs  M_{k+1}/k!
__device__ float g_cd[NC][BB];           // denominator coeffs M_k/k!
__device__ float g_alpha, g_gamma;

// alpha = sum_r tw*pw ; gamma = sum_r tb*pw
__global__ void k_setup(const float* __restrict__ tw, const float* __restrict__ tb,
                        const float* __restrict__ pw) {
    __shared__ float sa[64], sg[64];
    int r = threadIdx.x;
    sa[r] = tw[r] * pw[r];
    sg[r] = tb[r] * pw[r];
    __syncthreads();
    if (r == 0) {
        float A = 0.f, G = 0.f;
        for (int i = 0; i < 64; i++) { A += sa[i]; G += sg[i]; }
        g_alpha = A; g_gamma = G;
    }
}

// feature[b][m] -> XT[m][b]
__global__ void k_transpose(const float* __restrict__ f) {
    __shared__ float t[32][33];
    int m0 = blockIdx.x * 32, b0 = blockIdx.y * 32;
    int x = threadIdx.x, y = threadIdx.y;  // 32 x 8
#pragma unroll
    for (int j = 0; j < 32; j += 8) {
        int b = b0 + y + j, m = m0 + x;
        t[y + j][x] = (m < NN) ? f[b * NN + m] : 0.f;
    }
    __syncthreads();
#pragma unroll
    for (int j = 0; j < 32; j += 8) {
        int m = m0 + y + j, b = b0 + x;
        if (m < NN) g_XT[m * BB + b] = t[x][y + j];
    }
}

// per-batch power moments M_0..M_31, turned into Taylor coeffs
__global__ void k_moments(const float* __restrict__ feature) {
    int b = blockIdx.x;
    const float* xr = feature + b * NN;
    float acc[32];
#pragma unroll
    for (int k = 0; k < 32; k++) acc[k] = 0.f;
    for (int m = threadIdx.x; m < NN; m += 256) {
        float v = xr[m];
        float p = 1.f;
#pragma unroll
        for (int k = 0; k < 32; k++) { acc[k] += p; p *= v; }
    }
#pragma unroll
    for (int k = 0; k < 32; k++) {
#pragma unroll
        for (int off = 16; off > 0; off >>= 1)
            acc[k] += __shfl_down_sync(0xffffffffu, acc[k], off);
    }
    __shared__ float red[32][8];
    __shared__ float sM[32];
    int lane = threadIdx.x & 31, warp = threadIdx.x >> 5;
    if (lane == 0) {
#pragma unroll
        for (int k = 0; k < 32; k++) red[k][warp] = acc[k];
    }
    __syncthreads();
    if (threadIdx.x < 32) {
        float s = 0.f;
        for (int w = 0; w < 8; w++) s += red[threadIdx.x][w];
        sM[threadIdx.x] = s;
    }
    __syncthreads();
    if (threadIdx.x < NC) {
        int k = threadIdx.x;
        float fact = 1.f;
        for (int i = 2; i <= k; i++) fact *= (float)i;
        g_cd[k][b] = sM[k] / fact;
        g_cn[k][b] = sM[k + 1] / fact;
    }
}

// split-K fp32 GEMM: part[split][row][b] = sum_{m in split} A[row][m] * X[m][b]
// SEL=0: A=init_graph, X=g_XT, part=g_part1 ; SEL=1: A=fc1_w, X=g_mixedT, part=g_part2
template <int SEL>
__global__ __launch_bounds__(256) void k_gemm(const float* __restrict__ A,
                                              int nrows, int inner, int split_len) {
    const float* X = (SEL == 0) ? g_XT : g_mixedT;
    float* part = (SEL == 0) ? g_part1 : g_part2;
    __shared__ float sA[32][34];   // [m][row]
    __shared__ float sX[32][64];   // [m][b]
    int rb = blockIdx.x * 32;
    int m_begin = blockIdx.y * split_len;
    int m_end = m_begin + split_len;
    if (m_end > inner) m_end = inner;
    int tid = threadIdx.x;
    int tx = tid & 15;   // 4 b's each
    int ty = tid >> 4;   // 2 rows each
    float acc[2][4] = {{0.f, 0.f, 0.f, 0.f}, {0.f, 0.f, 0.f, 0.f}};
    for (int m0 = m_begin; m0 < m_end; m0 += 32) {
        {   // A tile 32 rows x 32 m (transposed into smem)
            int r = tid >> 3;
            int c = (tid & 7) * 4;
            int gr = rb + r, gm = m0 + c;
            float4 v = make_float4(0.f, 0.f, 0.f, 0.f);
            if (gr < nrows) {
                if (gm + 3 < m_end) {
                    v = *(const float4*)(A + (size_t)gr * inner + gm);
                } else {
                    float tv[4];
#pragma unroll
                    for (int k2 = 0; k2 < 4; k2++)
                        tv[k2] = (gm + k2 < m_end) ? A[(size_t)gr * inner + gm + k2] : 0.f;
                    v = make_float4(tv[0], tv[1], tv[2], tv[3]);
                }
            }
            sA[c + 0][r] = v.x; sA[c + 1][r] = v.y;
            sA[c + 2][r] = v.z; sA[c + 3][r] = v.w;
        }
        {   // X tile 32 m x 64 b
#pragma unroll
            for (int i = 0; i < 2; i++) {
                int f4 = tid + i * 256;
                int mm = f4 >> 4;
                int cb = (f4 & 15) * 4;
                int gm = m0 + mm;
                float4 v = (gm < m_end) ? *(const float4*)(X + (size_t)gm * BB + cb)
                                        : make_float4(0.f, 0.f, 0.f, 0.f);
                *(float4*)&sX[mm][cb] = v;
            }
        }
        __syncthreads();
#pragma unroll
        for (int k = 0; k < 32; k++) {
            float a0 = sA[k][ty * 2 + 0];
            float a1 = sA[k][ty * 2 + 1];
            float4 b4 = *(const float4*)&sX[k][tx * 4];
            acc[0][0] += a0 * b4.x; acc[0][1] += a0 * b4.y;
            acc[0][2] += a0 * b4.z; acc[0][3] += a0 * b4.w;
            acc[1][0] += a1 * b4.x; acc[1][1] += a1 * b4.y;
            acc[1][2] += a1 * b4.z; acc[1][3] += a1 * b4.w;
        }
        __syncthreads();
    }
    float* dst = part + (size_t)blockIdx.y * nrows * BB;
#pragma unroll
    for (int i = 0; i < 2; i++) {
        int gr = rb + ty * 2 + i;
        if (gr < nrows)
            *(float4*)(dst + (size_t)gr * BB + tx * 4) =
                make_float4(acc[i][0], acc[i][1], acc[i][2], acc[i][3]);
    }
}

// reduce IG-gemm partials + softmax-mix term g(s) + relu + residual -> mixedT[n][b]
__global__ void k_mix() {
    int idx = blockIdx.x * 256 + threadIdx.x;   // 500*256 == NN*BB exactly
    int b = idx & 63;
    float sum = g_part1[idx] + g_part1[NN * BB + idx] +
                g_part1[2 * NN * BB + idx] + g_part1[3 * NN * BB + idx];
    float x = g_XT[idx];
    float s = g_alpha * x + g_gamma;
    float P = g_cn[NC - 1][b], Q = g_cd[NC - 1][b];
#pragma unroll
    for (int k = NC - 2; k >= 0; k--) {
        P = P * s + g_cn[k][b];
        Q = Q * s + g_cd[k][b];
    }
    float g = P / Q;                 // = sum_m softmax(s*x)_m * x_m   (exact series)
    float rf = sum + g;
    rf = rf > 0.f ? rf : 0.f;
    g_mixedT[idx] = rf + x;
}

// reduce fc1 partials + bias + tanh -> hT[e][b]
__global__ void k_hid(const float* __restrict__ b1) {
    int idx = blockIdx.x * 256 + threadIdx.x;   // 128*256 == EMBED*BB
    int e = idx >> 6;
    float s = b1[e];
#pragma unroll
    for (int p = 0; p < 8; p++) s += g_part2[p * EMBED * BB + idx];
    g_hT[idx] = tanhf(s);
}

// logits[b][l] = sum_e w2[l][e] * hT[e][b] + b2[l]
__global__ void k_logits(const float* __restrict__ w2, const float* __restrict__ b2,
                         float* __restrict__ out) {
    int l = blockIdx.x;
    int b = threadIdx.x;
    const float* wr = w2 + l * EMBED;
    float a0 = 0.f, a1 = 0.f, a2 = 0.f, a3 = 0.f;
#pragma unroll 4
    for (int e = 0; e < EMBED; e += 4) {
        a0 += wr[e + 0] * g_hT[(e + 0) * BB + b];
        a1 += wr[e + 1] * g_hT[(e + 1) * BB + b];
        a2 += wr[e + 2] * g_hT[(e + 2) * BB + b];
        a3 += wr[e + 3] * g_hT[(e + 3) * BB + b];
    }
    out[b * LABELS + l] = a0 + a1 + a2 + a3 + b2[l];
}

extern "C" void kernel_launch(void* const* d_in, const int* in_sizes, int n_in,
                              void* d_out, int out_size) {
    const float* feature    = (const float*)d_in[0];
    const float* init_graph = (const float*)d_in[1];
    const float* theta_w    = (const float*)d_in[2];
    const float* theta_b    = (const float*)d_in[3];
    const float* phi_w      = (const float*)d_in[4];
    /* phi_b = d_in[5] cancels in the softmax */
    const float* fc1_w      = (const float*)d_in[6];
    const float* fc1_b      = (const float*)d_in[7];
    const float* fc2_w      = (const float*)d_in[8];
    const float* fc2_b      = (const float*)d_in[9];
    float* out = (float*)d_out;

    k_setup<<<1, 64>>>(theta_w, theta_b, phi_w);
    k_transpose<<<dim3(63, 2), dim3(32, 8)>>>(feature);
    k_moments<<<64, 256>>>(feature);
    k_gemm<0><<<dim3(63, 4), 256>>>(init_graph, NN, NN, 500);   // IG @ X^T (split-K 4)
    k_mix<<<500, 256>>>();
    k_gemm<1><<<dim3(16, 8), 256>>>(fc1_w, EMBED, NN, 256);     // fc1 (split-K 8)
    k_hid<<<128, 256>>>(fc1_b);
    k_logits<<<LABELS, BB>>>(fc2_w, fc2_b, out);
}

// round 3
// speedup vs baseline: 1.2000x; 1.2000x over previous
#include <cuda_runtime.h>
#include <math.h>

#define NN 2000
#define BB 64
#define EMBED 512
#define LABELS 20
#define NC 31   // Taylor degree 30

#define SPLIT0 4
#define SPLIT1 16

// ---- scratch ----
__device__ float g_XT[NN * BB];            // XT[m][b] (for k_mix)
__device__ float g_mixedT[NN * BB];        // mixedT[n][b]
__device__ float g_part1[SPLIT0 * NN * BB];
__device__ float g_part2[SPLIT1 * EMBED * BB];
__device__ float g_hT[EMBED * BB];
__device__ float g_cn[NC][BB];
__device__ float g_cd[NC][BB];
__device__ float g_alpha, g_gamma;

// fused: alpha/gamma setup + per-batch power moments + feature transpose
__global__ __launch_bounds__(256) void k_pre(const float* __restrict__ f,
                                             const float* __restrict__ tw,
                                             const float* __restrict__ tb,
                                             const float* __restrict__ pw) {
    int bid = blockIdx.x;
    if (bid < 64) {
        if (bid == 0) {
            __shared__ float sa[64], sg[64];
            if (threadIdx.x < 64) {
                sa[threadIdx.x] = tw[threadIdx.x] * pw[threadIdx.x];
                sg[threadIdx.x] = tb[threadIdx.x] * pw[threadIdx.x];
            }
            __syncthreads();
            if (threadIdx.x == 0) {
                float A = 0.f, G = 0.f;
                for (int i = 0; i < 64; i++) { A += sa[i]; G += sg[i]; }
                g_alpha = A; g_gamma = G;
            }
            __syncthreads();
        }
        int b = bid;
        const float* xr = f + b * NN;
        float acc[32];
#pragma unroll
        for (int k = 0; k < 32; k++) acc[k] = 0.f;
        for (int m = threadIdx.x; m < NN; m += 256) {
            float v = xr[m];
            float p = 1.f;
#pragma unroll
            for (int k = 0; k < 32; k++) { acc[k] += p; p *= v; }
        }
#pragma unroll
        for (int k = 0; k < 32; k++) {
#pragma unroll
            for (int off = 16; off > 0; off >>= 1)
                acc[k] += __shfl_down_sync(0xffffffffu, acc[k], off);
        }
        __shared__ float red[32][8];
        __shared__ float sM[32];
        int lane = threadIdx.x & 31, warp = threadIdx.x >> 5;
        if (lane == 0) {
#pragma unroll
            for (int k = 0; k < 32; k++) red[k][warp] = acc[k];
        }
        __syncthreads();
        if (threadIdx.x < 32) {
            float s = 0.f;
            for (int w = 0; w < 8; w++) s += red[threadIdx.x][w];
            sM[threadIdx.x] = s;
        }
        __syncthreads();
        if (threadIdx.x < NC) {
            int k = threadIdx.x;
            float fact = 1.f;
            for (int i = 2; i <= k; i++) fact *= (float)i;
            g_cd[k][b] = sM[k] / fact;
            g_cn[k][b] = sM[k + 1] / fact;
        }
    } else {
        // ---- transpose tile ----
        int t = bid - 64;              // 0..125
        int m0 = (t % 63) * 32, b0 = (t / 63) * 32;
        __shared__ float tt[32][33];
        int x = threadIdx.x & 31, y = threadIdx.x >> 5;   // 32 x 8
#pragma unroll
        for (int j = 0; j < 32; j += 8) {
            int b = b0 + y + j, m = m0 + x;
            tt[y + j][x] = (m < NN) ? f[b * NN + m] : 0.f;
        }
        __syncthreads();
#pragma unroll
        for (int j = 0; j < 32; j += 8) {
            int m = m0 + y + j, b = b0 + x;
            if (m < NN) g_XT[m * BB + b] = tt[x][y + j];
        }
    }
}

// 64x64x16-tiled split-K fp32 GEMM, register->smem double buffered.
// split_len MUST be a multiple of 16 (alignment of float4 global loads).
// SEL=0: A=init_graph [NN,NN], X=feature[b][k] (transposed on load), part=g_part1
// SEL=1: A=fc1_w [EMBED,NN],  X=g_mixedT [k][b],                    part=g_part2
template <int SEL>
__global__ __launch_bounds__(256) void k_gemm(const float* __restrict__ A,
                                              const float* __restrict__ F,
                                              int nrows, int inner, int split_len) {
    __shared__ __align__(16) float sA[2][16][68];
    __shared__ __align__(16) float sX[2][16][68];
    float* part = (SEL == 0) ? g_part1 : g_part2;
    const float* Xp = (SEL == 0) ? F : (const float*)g_mixedT;

    const int tid = threadIdx.x;
    const int rb = blockIdx.x * 64;
    const int kb = blockIdx.y * split_len;
    int ke = kb + split_len; if (ke > inner) ke = inner;
    const int niter = (ke - kb + 15) >> 4;

    const int tx = tid & 15;          // 4 cols each
    const int ty = tid >> 4;          // 4 rows each
    const int lr = tid >> 2;          // A: row 0..63
    const int lk = (tid & 3) << 2;    // A: k 0,4,8,12
    const int xb = (SEL == 0) ? (tid >> 2) : ((tid & 15) << 2);
    const int xk = (SEL == 0) ? ((tid & 3) << 2) : (tid >> 4);

    float acc[4][4];
#pragma unroll
    for (int i = 0; i < 4; i++)
#pragma unroll
        for (int j = 0; j < 4; j++) acc[i][j] = 0.f;

    auto ldA = [&](int k0) -> float4 {
        float4 v = make_float4(0.f, 0.f, 0.f, 0.f);
        int ar = rb + lr, kk = k0 + lk;
        if (ar < nrows) {
            if (kk + 4 <= ke) {
                v = *(const float4*)(A + (size_t)ar * inner + kk);
            } else {
                float* pv = &v.x;
#pragma unroll
                for (int j = 0; j < 4; j++)
                    if (kk + j < ke) pv[j] = A[(size_t)ar * inner + kk + j];
            }
        }
        return v;
    };
    auto ldX = [&](int k0) -> float4 {
        float4 v = make_float4(0.f, 0.f, 0.f, 0.f);
        int kk = k0 + xk;
        if (SEL == 0) {
            if (kk + 4 <= ke) {
                v = *(const float4*)(Xp + (size_t)xb * inner + kk);
            } else {
                float* pv = &v.x;
#pragma unroll
                for (int j = 0; j < 4; j++)
                    if (kk + j < ke) pv[j] = Xp[(size_t)xb * inner + kk + j];
            }
        } else {
            if (kk < ke) v = *(const float4*)(Xp + (size_t)kk * BB + xb);
        }
        return v;
    };
    auto sts = [&](int buf, float4 a, float4 x) {
        sA[buf][lk + 0][lr] = a.x; sA[buf][lk + 1][lr] = a.y;
        sA[buf][lk + 2][lr] = a.z; sA[buf][lk + 3][lr] = a.w;
        if (SEL == 0) {
            sX[buf][xk + 0][xb] = x.x; sX[buf][xk + 1][xb] = x.y;
            sX[buf][xk + 2][xb] = x.z; sX[buf][xk + 3][xb] = x.w;
        } else {
            *(float4*)&sX[buf][xk][xb] = x;
        }
    };

    float4 pa = ldA(kb), px = ldX(kb);
    sts(0, pa, px);
    __syncthreads();
    int buf = 0;
    for (int it = 0; it < niter; ++it) {
        float4 na, nx;
        bool more = (it + 1 < niter);
        if (more) { int k0n = kb + (it + 1) * 16; na = ldA(k0n); nx = ldX(k0n); }
#pragma unroll
        for (int kk = 0; kk < 16; kk++) {
            float4 a = *(const float4*)&sA[buf][kk][ty * 4];
            float4 x = *(const float4*)&sX[buf][kk][tx * 4];
            acc[0][0] += a.x * x.x; acc[0][1] += a.x * x.y; acc[0][2] += a.x * x.z; acc[0][3] += a.x * x.w;
            acc[1][0] += a.y * x.x; acc[1][1] += a.y * x.y; acc[1][2] += a.y * x.z; acc[1][3] += a.y * x.w;
            acc[2][0] += a.z * x.x; acc[2][1] += a.z * x.y; acc[2][2] += a.z * x.z; acc[2][3] += a.z * x.w;
            acc[3][0] += a.w * x.x; acc[3][1] += a.w * x.y; acc[3][2] += a.w * x.z; acc[3][3] += a.w * x.w;
        }
        if (more) {
            sts(buf ^ 1, na, nx);
            __syncthreads();
            buf ^= 1;
        }
    }

    float* dst = part + (size_t)blockIdx.y * nrows * BB;
#pragma unroll
    for (int i = 0; i < 4; i++) {
        int r = rb + ty * 4 + i;
        if (r < nrows)
            *(float4*)(dst + (size_t)r * BB + tx * 4) =
                make_float4(acc[i][0], acc[i][1], acc[i][2], acc[i][3]);
    }
}

// reduce IG-gemm partials + exact softmax-mix term g(s) + relu + residual -> mixedT[n][b]
__global__ void k_mix() {
    int idx = blockIdx.x * 256 + threadIdx.x;   // 500*256 == NN*BB
    int b = idx & 63;
    float sum = g_part1[idx] + g_part1[NN * BB + idx] +
                g_part1[2 * NN * BB + idx] + g_part1[3 * NN * BB + idx];
    float x = g_XT[idx];
    float s = g_alpha * x + g_gamma;
    float P = g_cn[NC - 1][b], Q = g_cd[NC - 1][b];
#pragma unroll
    for (int k = NC - 2; k >= 0; k--) {
        P = P * s + g_cn[k][b];
        Q = Q * s + g_cd[k][b];
    }
    float g = P / Q;
    float rf = sum + g;
    rf = rf > 0.f ? rf : 0.f;
    g_mixedT[idx] = rf + x;
}

// reduce fc1 partials + bias + tanh -> hT[e][b]
__global__ void k_hid(const float* __restrict__ b1) {
    int idx = blockIdx.x * 256 + threadIdx.x;   // 128*256 == EMBED*BB
    int e = idx >> 6;
    float s = b1[e];
#pragma unroll
    for (int p = 0; p < SPLIT1; p++) s += g_part2[p * EMBED * BB + idx];
    g_hT[idx] = tanhf(s);
}

// logits[b][l] = sum_e w2[l][e] * hT[e][b] + b2[l]
__global__ void k_logits(const float* __restrict__ w2, const float* __restrict__ b2,
                         float* __restrict__ out) {
    int l = blockIdx.x;
    int b = threadIdx.x;
    const float* wr = w2 + l * EMBED;
    float a0 = 0.f, a1 = 0.f, a2 = 0.f, a3 = 0.f;
#pragma unroll 4
    for (int e = 0; e < EMBED; e += 4) {
        a0 += wr[e + 0] * g_hT[(e + 0) * BB + b];
        a1 += wr[e + 1] * g_hT[(e + 1) * BB + b];
        a2 += wr[e + 2] * g_hT[(e + 2) * BB + b];
        a3 += wr[e + 3] * g_hT[(e + 3) * BB + b];
    }
    out[b * LABELS + l] = a0 + a1 + a2 + a3 + b2[l];
}

extern "C" void kernel_launch(void* const* d_in, const int* in_sizes, int n_in,
                              void* d_out, int out_size) {
    const float* feature    = (const float*)d_in[0];
    const float* init_graph = (const float*)d_in[1];
    const float* theta_w    = (const float*)d_in[2];
    const float* theta_b    = (const float*)d_in[3];
    const float* phi_w      = (const float*)d_in[4];
    /* phi_b cancels in the softmax */
    const float* fc1_w      = (const float*)d_in[6];
    const float* fc1_b      = (const float*)d_in[7];
    const float* fc2_w      = (const float*)d_in[8];
    const float* fc2_b      = (const float*)d_in[9];
    float* out = (float*)d_out;

    k_pre<<<190, 256>>>(feature, theta_w, theta_b, phi_w);
    // split_len 500: multiple of 4 AND start offsets (0,500,1000,1500) mult of 4;
    // all k-tile starts kb+16*it stay 4-aligned since 500%4==0. float4 global loads in
    // ldA/ldX need 16B alignment -> require kb%4==0 and inner%4==0 (2000%4==0). OK.
    k_gemm<0><<<dim3(32, SPLIT0), 256>>>(init_graph, feature, NN, NN, 500);
    k_mix<<<500, 256>>>();
    // split_len 128 (multiple of 16): kb in {0,128,...,1920}; last split covers 80.
    k_gemm<1><<<dim3(8, SPLIT1), 256>>>(fc1_w, nullptr, EMBED, NN, 128);
    k_hid<<<128, 256>>>(fc1_b);
    k_logits<<<LABELS, BB>>>(fc2_w, fc2_b, out);
}

// round 5
// speedup vs baseline: 1.8208x; 1.5174x over previous
#include <cuda_runtime.h>
#include <cuda_bf16.h>
#include <math.h>
#include <stdint.h>

#define NN 2000
#define BB 64
#define EMBED 512
#define LABELS 20
#define NC 31            // Taylor degree 30

#define MT 128           // gemm0 M tile
#define NMT 16
#define SPLIT0 9
#define SPLEN0 224
#define G0_BLOCKS (NMT * SPLIT0)   // 144
#define SPLIT1 16

// smem tile layout (bf16, rows padded to 72 elements = 144B):
//  Ahi: 128x72 (18432B)  Alo: 18432  Bhi: 64x72 (9216)  Blo: 9216  => 55296/buf
#define A_PAD 72
#define OFF_ALO 18432
#define OFF_BHI 36864
#define OFF_BLO 46080
#define BUF_STRIDE 55296
#define DSMEM (2 * BUF_STRIDE)

// ---- scratch ----
__device__ float g_XT[NN * BB];
__device__ float g_mixedT[NN * BB];
__device__ float g_part1[SPLIT0 * NN * BB];
__device__ float g_part2[SPLIT1 * EMBED * BB];
__device__ float g_hT[EMBED * BB];
__device__ float g_cn[NC][BB];
__device__ float g_cd[NC][BB];
__device__ float g_alpha, g_gamma;

__device__ __forceinline__ void mma16816(float* d, const uint32_t* a, const uint32_t* b) {
    asm volatile(
        "mma.sync.aligned.m16n8k16.row.col.f32.bf16.bf16.f32 "
        "{%0,%1,%2,%3}, {%4,%5,%6,%7}, {%8,%9}, {%0,%1,%2,%3};\n"
        : "+f"(d[0]), "+f"(d[1]), "+f"(d[2]), "+f"(d[3])
        : "r"(a[0]), "r"(a[1]), "r"(a[2]), "r"(a[3]), "r"(b[0]), "r"(b[1]));
}

// float4 -> bf16 hi + bf16 lo, stored at [row][k] (pad A_PAD). byte off 8-aligned.
__device__ __forceinline__ void split_store(char* hi, char* lo, int byte, float4 v) {
    __nv_bfloat16 hx = __float2bfloat16(v.x), hy = __float2bfloat16(v.y);
    __nv_bfloat16 hz = __float2bfloat16(v.z), hw = __float2bfloat16(v.w);
    float lx = v.x - __bfloat162float(hx), ly = v.y - __bfloat162float(hy);
    float lz = v.z - __bfloat162float(hz), lw = v.w - __bfloat162float(hw);
    uint2 h2, l2;
    h2.x = (unsigned)__bfloat16_as_ushort(hx) | ((unsigned)__bfloat16_as_ushort(hy) << 16);
    h2.y = (unsigned)__bfloat16_as_ushort(hz) | ((unsigned)__bfloat16_as_ushort(hw) << 16);
    __nv_bfloat16 ax = __float2bfloat16(lx), ay = __float2bfloat16(ly);
    __nv_bfloat16 az = __float2bfloat16(lz), aw = __float2bfloat16(lw);
    l2.x = (unsigned)__bfloat16_as_ushort(ax) | ((unsigned)__bfloat16_as_ushort(ay) << 16);
    l2.y = (unsigned)__bfloat16_as_ushort(az) | ((unsigned)__bfloat16_as_ushort(aw) << 16);
    *(uint2*)(hi + byte) = h2;
    *(uint2*)(lo + byte) = l2;
}

// ============================================================================
// Fused: mma.sync bf16-split gemm0 (blocks 0..143) + moments (144..207)
//        + transpose (208..333)
// ============================================================================
__global__ __launch_bounds__(256, 1)
void k_main(const float* __restrict__ IG, const float* __restrict__ feat,
            const float* __restrict__ tw, const float* __restrict__ tb,
            const float* __restrict__ pw) {
    extern __shared__ __align__(16) char dsm[];
    const int bid = blockIdx.x;
    const int tid = threadIdx.x;

    if (bid < G0_BLOCKS) {
        const int wid = tid >> 5, lane = tid & 31;
        const int mt = bid & 15, sp = bid >> 4;       // 16 mtiles x 9 splits
        const int rb = mt * MT;
        const int kb = sp * SPLEN0;
        int ke = kb + SPLEN0; if (ke > NN) ke = NN;
        const int nc = (ke - kb + 63) >> 6;           // 4

        const int warp_m = wid >> 1;                  // 0..3
        const int warp_n = wid & 1;                   // 0..1
        const int g = lane >> 2, tig = lane & 3;

        // load indices
        const int ar = tid >> 1, hh = tid & 1;        // A: row, k-half
        const int brr = tid >> 2, qq = tid & 3;       // B: b-row, k-quarter
        const bool rok = (rb + ar) < NN;
        const float* arow = IG + (size_t)(rb + ar) * NN;
        const float* brow = feat + (size_t)brr * NN;

        float acc[2][4][4];
#pragma unroll
        for (int t = 0; t < 2; t++)
#pragma unroll
            for (int u = 0; u < 4; u++)
#pragma unroll
                for (int j = 0; j < 4; j++) acc[t][u][j] = 0.f;

        float4 ra[8], rb4[4];
        auto ldg_chunk = [&](int c) {
            int m0 = kb + c * 64;
            int mlen = ke - m0; if (mlen > 64) mlen = 64;
#pragma unroll
            for (int i = 0; i < 8; i++) {
                int kk = hh * 32 + i * 4;
                float4 v = make_float4(0.f, 0.f, 0.f, 0.f);
                if (rok) {
                    if (kk + 4 <= mlen) v = *(const float4*)(arow + m0 + kk);
                    else if (kk < mlen) {
                        float* pv = &v.x;
#pragma unroll
                        for (int j = 0; j < 4; j++)
                            if (kk + j < mlen) pv[j] = arow[m0 + kk + j];
                    }
                }
                ra[i] = v;
            }
#pragma unroll
            for (int i = 0; i < 4; i++) {
                int kk = qq * 16 + i * 4;
                float4 v = make_float4(0.f, 0.f, 0.f, 0.f);
                if (kk + 4 <= mlen) v = *(const float4*)(brow + m0 + kk);
                else if (kk < mlen) {
                    float* pv = &v.x;
#pragma unroll
                    for (int j = 0; j < 4; j++)
                        if (kk + j < mlen) pv[j] = brow[m0 + kk + j];
                }
                rb4[i] = v;
            }
        };
        auto cvt_store = [&](int p) {
            char* base = dsm + p * BUF_STRIDE;
            char* Ahi = base;            char* Alo = base + OFF_ALO;
            char* Bhi = base + OFF_BHI;  char* Blo = base + OFF_BLO;
#pragma unroll
            for (int i = 0; i < 8; i++) {
                int kk = hh * 32 + i * 4;
                split_store(Ahi, Alo, ar * (A_PAD * 2) + kk * 2, ra[i]);
            }
#pragma unroll
            for (int i = 0; i < 4; i++) {
                int kk = qq * 16 + i * 4;
                split_store(Bhi, Blo, brr * (A_PAD * 2) + kk * 2, rb4[i]);
            }
        };
        auto compute = [&](int p) {
            char* base = dsm + p * BUF_STRIDE;
            char* Ahi = base;            char* Alo = base + OFF_ALO;
            char* Bhi = base + OFF_BHI;  char* Blo = base + OFF_BLO;
#pragma unroll
            for (int ks = 0; ks < 4; ks++) {
                const int ko = ks * 16;
                uint32_t ah[2][4], al[2][4], bh[4][2], bl[4][2];
#pragma unroll
                for (int t = 0; t < 2; t++) {
                    int row = warp_m * 32 + t * 16 + g;
                    int o0 = row * (A_PAD * 2) + (ko + tig * 2) * 2;
                    int o1 = (row + 8) * (A_PAD * 2) + (ko + tig * 2) * 2;
                    ah[t][0] = *(uint32_t*)(Ahi + o0);
                    ah[t][1] = *(uint32_t*)(Ahi + o1);
                    ah[t][2] = *(uint32_t*)(Ahi + o0 + 16);
                    ah[t][3] = *(uint32_t*)(Ahi + o1 + 16);
                    al[t][0] = *(uint32_t*)(Alo + o0);
                    al[t][1] = *(uint32_t*)(Alo + o1);
                    al[t][2] = *(uint32_t*)(Alo + o0 + 16);
                    al[t][3] = *(uint32_t*)(Alo + o1 + 16);
                }
#pragma unroll
                for (int u = 0; u < 4; u++) {
                    int col = warp_n * 32 + u * 8 + g;
                    int o = col * (A_PAD * 2) + (ko + tig * 2) * 2;
                    bh[u][0] = *(uint32_t*)(Bhi + o);
                    bh[u][1] = *(uint32_t*)(Bhi + o + 16);
                    bl[u][0] = *(uint32_t*)(Blo + o);
                    bl[u][1] = *(uint32_t*)(Blo + o + 16);
                }
#pragma unroll
                for (int t = 0; t < 2; t++)
#pragma unroll
                    for (int u = 0; u < 4; u++) {
                        mma16816(acc[t][u], ah[t], bh[u]);
                        mma16816(acc[t][u], ah[t], bl[u]);
                        mma16816(acc[t][u], al[t], bh[u]);
                    }
            }
        };

        ldg_chunk(0);
        for (int c = 0; c < nc; c++) {
            int p = c & 1;
            cvt_store(p);
            if (c + 1 < nc) ldg_chunk(c + 1);
            __syncthreads();
            compute(p);
        }

        // epilogue
        float* dst = g_part1 + (size_t)sp * NN * BB;
#pragma unroll
        for (int t = 0; t < 2; t++) {
            int r0 = rb + warp_m * 32 + t * 16 + g;
#pragma unroll
            for (int u = 0; u < 4; u++) {
                int cn = warp_n * 32 + u * 8 + tig * 2;
                if (r0 < NN)
                    *(float2*)(dst + (size_t)r0 * BB + cn) = make_float2(acc[t][u][0], acc[t][u][1]);
                if (r0 + 8 < NN)
                    *(float2*)(dst + (size_t)(r0 + 8) * BB + cn) = make_float2(acc[t][u][2], acc[t][u][3]);
            }
        }
        return;
    }

    const int pid = bid - G0_BLOCKS;
    if (pid < 64) {
        // ---------------- moments (+ alpha/gamma on pid==0) ----------------
        if (pid == 0) {
            __shared__ float sa[64], sg[64];
            if (tid < 64) {
                sa[tid] = tw[tid] * pw[tid];
                sg[tid] = tb[tid] * pw[tid];
            }
            __syncthreads();
            if (tid == 0) {
                float A = 0.f, G = 0.f;
                for (int i = 0; i < 64; i++) { A += sa[i]; G += sg[i]; }
                g_alpha = A; g_gamma = G;
            }
            __syncthreads();
        }
        int b = pid;
        const float* xr = feat + b * NN;
        float acc[32];
#pragma unroll
        for (int k = 0; k < 32; k++) acc[k] = 0.f;
        for (int m = tid; m < NN; m += 256) {
            float v = xr[m];
            float pw2 = 1.f;
#pragma unroll
            for (int k = 0; k < 32; k++) { acc[k] += pw2; pw2 *= v; }
        }
#pragma unroll
        for (int k = 0; k < 32; k++) {
#pragma unroll
            for (int off = 16; off > 0; off >>= 1)
                acc[k] += __shfl_down_sync(0xffffffffu, acc[k], off);
        }
        __shared__ float red[32][8];
        __shared__ float sM[32];
        int lane = tid & 31, warp = tid >> 5;
        if (lane == 0) {
#pragma unroll
            for (int k = 0; k < 32; k++) red[k][warp] = acc[k];
        }
        __syncthreads();
        if (tid < 32) {
            float s = 0.f;
            for (int w = 0; w < 8; w++) s += red[tid][w];
            sM[tid] = s;
        }
        __syncthreads();
        if (tid < NC) {
            int k = tid;
            float fact = 1.f;
            for (int i = 2; i <= k; i++) fact *= (float)i;
            g_cd[k][b] = sM[k] / fact;
            g_cn[k][b] = sM[k + 1] / fact;
        }
    } else {
        // ---------------- transpose tile ----------------
        int t = pid - 64;                  // 0..125
        int m0 = (t % 63) * 32, b0 = (t / 63) * 32;
        __shared__ float tt[32][33];
        int x = tid & 31, y = tid >> 5;    // 32 x 8
#pragma unroll
        for (int j = 0; j < 32; j += 8) {
            int b = b0 + y + j, m = m0 + x;
            tt[y + j][x] = (m < NN) ? feat[b * NN + m] : 0.f;
        }
        __syncthreads();
#pragma unroll
        for (int j = 0; j < 32; j += 8) {
            int m = m0 + y + j, b = b0 + x;
            if (m < NN) g_XT[m * BB + b] = tt[x][y + j];
        }
    }
}

// reduce gemm0 partials + exact softmax-mix term g(s) + relu + residual
__global__ void k_mix() {
    int idx = blockIdx.x * 256 + threadIdx.x;   // 500*256 == NN*BB
    int b = idx & 63;
    float sum = 0.f;
#pragma unroll
    for (int p = 0; p < SPLIT0; p++) sum += g_part1[p * NN * BB + idx];
    float x = g_XT[idx];
    float s = g_alpha * x + g_gamma;
    float P = g_cn[NC - 1][b], Q = g_cd[NC - 1][b];
#pragma unroll
    for (int k = NC - 2; k >= 0; k--) {
        P = P * s + g_cn[k][b];
        Q = Q * s + g_cd[k][b];
    }
    float g = P / Q;
    float rf = sum + g;
    rf = rf > 0.f ? rf : 0.f;
    g_mixedT[idx] = rf + x;
}

// fc1 split-K GEMM: 32x64 tile, 128 threads, double buffered
__global__ __launch_bounds__(128) void k_gemm1(const float* __restrict__ W) {
    __shared__ __align__(16) float sA[2][16][36];
    __shared__ __align__(16) float sX[2][16][68];
    const int tid = threadIdx.x;
    const int rb = blockIdx.x * 32;
    const int kb = blockIdx.y * 128;
    int ke = kb + 128; if (ke > NN) ke = NN;
    const int niter = (ke - kb + 15) >> 4;

    const int tx = tid & 15;
    const int ty = tid >> 4;
    const int lr = tid >> 2;
    const int lk = (tid & 3) << 2;
    const int xb = (tid & 15) << 2;
    const int xk = tid >> 4;

    float acc[4][4];
#pragma unroll
    for (int i = 0; i < 4; i++)
#pragma unroll
        for (int j = 0; j < 4; j++) acc[i][j] = 0.f;

    auto ldA = [&](int k0) -> float4 {
        int kk = k0 + lk;
        if (kk + 4 <= ke) return *(const float4*)(W + (size_t)(rb + lr) * NN + kk);
        float4 v = make_float4(0.f, 0.f, 0.f, 0.f);
        float* pv = &v.x;
#pragma unroll
        for (int j = 0; j < 4; j++)
            if (kk + j < ke) pv[j] = W[(size_t)(rb + lr) * NN + kk + j];
        return v;
    };
    auto ldX = [&](int k0, int kof) -> float4 {
        int kk = k0 + xk + kof;
        if (kk < ke) return *(const float4*)(g_mixedT + (size_t)kk * BB + xb);
        return make_float4(0.f, 0.f, 0.f, 0.f);
    };
    auto sts = [&](int buf, float4 a, float4 x0, float4 x1) {
        sA[buf][lk + 0][lr] = a.x; sA[buf][lk + 1][lr] = a.y;
        sA[buf][lk + 2][lr] = a.z; sA[buf][lk + 3][lr] = a.w;
        *(float4*)&sX[buf][xk][xb] = x0;
        *(float4*)&sX[buf][xk + 8][xb] = x1;
    };

    float4 pa = ldA(kb), p0 = ldX(kb, 0), p1 = ldX(kb, 8);
    sts(0, pa, p0, p1);
    __syncthreads();
    int buf = 0;
    for (int it = 0; it < niter; ++it) {
        float4 na, n0, n1;
        bool more = (it + 1 < niter);
        if (more) {
            int k0n = kb + (it + 1) * 16;
            na = ldA(k0n); n0 = ldX(k0n, 0); n1 = ldX(k0n, 8);
        }
#pragma unroll
        for (int kk = 0; kk < 16; kk++) {
            float4 a = *(const float4*)&sA[buf][kk][ty * 4];
            float4 x = *(const float4*)&sX[buf][kk][tx * 4];
            acc[0][0] += a.x * x.x; acc[0][1] += a.x * x.y; acc[0][2] += a.x * x.z; acc[0][3] += a.x * x.w;
            acc[1][0] += a.y * x.x; acc[1][1] += a.y * x.y; acc[1][2] += a.y * x.z; acc[1][3] += a.y * x.w;
            acc[2][0] += a.z * x.x; acc[2][1] += a.z * x.y; acc[2][2] += a.z * x.z; acc[2][3] += a.z * x.w;
            acc[3][0] += a.w * x.x; acc[3][1] += a.w * x.y; acc[3][2] += a.w * x.z; acc[3][3] += a.w * x.w;
        }
        if (more) {
            sts(buf ^ 1, na, n0, n1);
            __syncthreads();
            buf ^= 1;
        }
    }
    float* dst = g_part2 + (size_t)blockIdx.y * EMBED * BB;
#pragma unroll
    for (int i = 0; i < 4; i++) {
        int rr = rb + ty * 4 + i;
        *(float4*)(dst + (size_t)rr * BB + tx * 4) =
            make_float4(acc[i][0], acc[i][1], acc[i][2], acc[i][3]);
    }
}

// reduce fc1 partials + bias + tanh -> hT[e][b]
__global__ void k_hid(const float* __restrict__ b1) {
    int idx = blockIdx.x * 256 + threadIdx.x;   // 128*256 == EMBED*BB
    int e = idx >> 6;
    float s = b1[e];
#pragma unroll
    for (int p = 0; p < SPLIT1; p++) s += g_part2[p * EMBED * BB + idx];
    g_hT[idx] = tanhf(s);
}

// logits[b][l] = sum_e w2[l][e] * hT[e][b] + b2[l]
__global__ void k_logits(const float* __restrict__ w2, const float* __restrict__ b2,
                         float* __restrict__ out) {
    int l = blockIdx.x;
    int t = threadIdx.x;
    int b = t & 63, q = t >> 6;
    const float* wr = w2 + l * EMBED + q * 128;
    const float* hp = g_hT + (q * 128) * BB + b;
    float acc = 0.f;
#pragma unroll 8
    for (int e = 0; e < 128; e++) acc += wr[e] * hp[e * BB];
    __shared__ float s[256];
    s[t] = acc;
    __syncthreads();
    if (q == 0)
        out[b * LABELS + l] = s[b] + s[64 + b] + s[128 + b] + s[192 + b] + b2[l];
}

extern "C" void kernel_launch(void* const* d_in, const int* in_sizes, int n_in,
                              void* d_out, int out_size) {
    const float* feature    = (const float*)d_in[0];
    const float* init_graph = (const float*)d_in[1];
    const float* theta_w    = (const float*)d_in[2];
    const float* theta_b    = (const float*)d_in[3];
    const float* phi_w      = (const float*)d_in[4];
    /* phi_b cancels in the softmax */
    const float* fc1_w      = (const float*)d_in[6];
    const float* fc1_b      = (const float*)d_in[7];
    const float* fc2_w      = (const float*)d_in[8];
    const float* fc2_b      = (const float*)d_in[9];
    float* out = (float*)d_out;

    static int smem_set = 0;
    if (!smem_set) {
        cudaFuncSetAttribute(k_main, cudaFuncAttributeMaxDynamicSharedMemorySize, DSMEM);
        smem_set = 1;
    }

    k_main<<<G0_BLOCKS + 64 + 126, 256, DSMEM>>>(init_graph, feature, theta_w, theta_b, phi_w);
    k_mix<<<500, 256>>>();
    k_gemm1<<<dim3(16, SPLIT1), 128>>>(fc1_w);
    k_hid<<<128, 256>>>(fc1_b);
    k_logits<<<LABELS, 256>>>(fc2_w, fc2_b, out);
}